// round 16
// baseline (speedup 1.0000x reference)
#include <cuda_runtime.h>
#include <cuda_bf16.h>
#include <cstdint>

#define M    100000
#define NQ   256
#define D    128
#define KNN  100
#define BB   4
#define TT   64
#define CAP  4096
#define TSTR 136          // smem tile stride in bf16 elems
#define NTRANS (BB * (TT - 1))   // 252 slabs

// ---------------- device scratch ----------------
static __device__ float          g_tn[M];
static __device__ unsigned short g_key16[(size_t)NQ * M];
static __device__ int            g_idx[NQ * KNN];
static __device__ float          g_emit[NQ * KNN];
static __device__ float          g_trans[(size_t)NTRANS * KNN * KNN];
static __device__ int            g_flag[NTRANS];

__device__ __forceinline__ unsigned int f2key(float f) {
    unsigned int u = __float_as_uint(f);
    return (u & 0x80000000u) ? ~u : (u | 0x80000000u);
}
__device__ __forceinline__ float key2f(unsigned int k) {
    unsigned int u = (k & 0x80000000u) ? (k & 0x7fffffffu) : ~k;
    return __uint_as_float(u);
}

__device__ __forceinline__ void mma_bf16(float* d, const unsigned* a, const unsigned* b) {
    asm volatile(
        "mma.sync.aligned.m16n8k16.row.col.f32.bf16.bf16.f32 "
        "{%0,%1,%2,%3}, {%4,%5,%6,%7}, {%8,%9}, {%0,%1,%2,%3};"
        : "+f"(d[0]), "+f"(d[1]), "+f"(d[2]), "+f"(d[3])
        : "r"(a[0]), "r"(a[1]), "r"(a[2]), "r"(a[3]), "r"(b[0]), "r"(b[1]));
}

// ---------------- flag reset (each graph replay) ----------------
__global__ void reset_kernel() {
    int i = threadIdx.x;
    for (; i < NTRANS; i += 256) g_flag[i] = 0;
}

// ---------------- fused dist (unchanged, proven) ----------------
__global__ __launch_bounds__(256)
void dist_bf16_kernel(const float* __restrict__ Q, const float* __restrict__ Tg) {
    extern __shared__ __align__(16) char dyn[];
    __nv_bfloat16* Qs = (__nv_bfloat16*)dyn;
    __nv_bfloat16* Ts = Qs + 128 * TSTR;
    __shared__ float s_qn[128], s_tn[128];
    int tid = threadIdx.x;
    int lane = tid & 31;
    int q0 = blockIdx.y * 128, t0 = blockIdx.x * 128;

    for (int it = 0; it < 16; it++) {
        int r = it * 8 + (tid >> 5);
        int c4 = lane * 4;
        float4 v = *(const float4*)&Q[(size_t)(q0 + r) * D + c4];
        float pn = v.x * v.x + v.y * v.y + v.z * v.z + v.w * v.w;
        __nv_bfloat162 p0 = __floats2bfloat162_rn(v.x, v.y);
        __nv_bfloat162 p1 = __floats2bfloat162_rn(v.z, v.w);
        *(uint2*)&Qs[r * TSTR + c4] = make_uint2(*(unsigned*)&p0, *(unsigned*)&p1);
#pragma unroll
        for (int off = 16; off > 0; off >>= 1) pn += __shfl_xor_sync(0xFFFFFFFFu, pn, off);
        if (lane == 0) s_qn[r] = pn;
        float4 tv = make_float4(0.f, 0.f, 0.f, 0.f);
        if (t0 + r < M) tv = *(const float4*)&Tg[(size_t)(t0 + r) * D + c4];
        float tn = tv.x * tv.x + tv.y * tv.y + tv.z * tv.z + tv.w * tv.w;
        __nv_bfloat162 t0b = __floats2bfloat162_rn(tv.x, tv.y);
        __nv_bfloat162 t1b = __floats2bfloat162_rn(tv.z, tv.w);
        *(uint2*)&Ts[r * TSTR + c4] = make_uint2(*(unsigned*)&t0b, *(unsigned*)&t1b);
#pragma unroll
        for (int off = 16; off > 0; off >>= 1) tn += __shfl_xor_sync(0xFFFFFFFFu, tn, off);
        if (lane == 0) s_tn[r] = tn;
    }

    if (blockIdx.y == 0 && tid < 128 && t0 + tid < M) {
        const float4* p = (const float4*)(Tg + (size_t)(t0 + tid) * D);
        float acc = 0.f;
#pragma unroll
        for (int k = 0; k < 32; k++) {
            float4 v = p[k];
            acc += v.x * v.x + v.y * v.y + v.z * v.z + v.w * v.w;
        }
        g_tn[t0 + tid] = acc;
    }
    __syncthreads();

    int wid = tid >> 5;
    int g = lane >> 2, t = lane & 3;
    int m0 = (wid >> 1) * 32, n0 = (wid & 1) * 64;

    float acc[2][8][4];
#pragma unroll
    for (int mi = 0; mi < 2; mi++)
#pragma unroll
        for (int ni = 0; ni < 8; ni++)
#pragma unroll
            for (int r = 0; r < 4; r++) acc[mi][ni][r] = 0.f;

#pragma unroll
    for (int ks = 0; ks < 8; ks++) {
        int k0 = ks * 16;
        unsigned a[2][4], b[8][2];
#pragma unroll
        for (int mi = 0; mi < 2; mi++) {
            const __nv_bfloat16* base = &Qs[(m0 + mi * 16 + g) * TSTR + k0 + 2 * t];
            a[mi][0] = *(const unsigned*)(base);
            a[mi][1] = *(const unsigned*)(base + 8 * TSTR);
            a[mi][2] = *(const unsigned*)(base + 8);
            a[mi][3] = *(const unsigned*)(base + 8 * TSTR + 8);
        }
#pragma unroll
        for (int ni = 0; ni < 8; ni++) {
            const __nv_bfloat16* base = &Ts[(n0 + ni * 8 + g) * TSTR + k0 + 2 * t];
            b[ni][0] = *(const unsigned*)(base);
            b[ni][1] = *(const unsigned*)(base + 8);
        }
#pragma unroll
        for (int mi = 0; mi < 2; mi++)
#pragma unroll
            for (int ni = 0; ni < 8; ni++)
                mma_bf16(acc[mi][ni], a[mi], b[ni]);
    }

#pragma unroll
    for (int mi = 0; mi < 2; mi++)
#pragma unroll
        for (int half = 0; half < 2; half++) {
            int qr = m0 + mi * 16 + g + half * 8;
            float qn = s_qn[qr];
            unsigned int* dst32 = (unsigned int*)(g_key16 + (size_t)(q0 + qr) * M);
#pragma unroll
            for (int ni = 0; ni < 8; ni++) {
                int tc = n0 + ni * 8 + 2 * t;
                int gtc = t0 + tc;
                if (gtc + 1 < M) {
                    float d0 = qn + s_tn[tc]     - 2.f * acc[mi][ni][half * 2 + 0];
                    float d1 = qn + s_tn[tc + 1] - 2.f * acc[mi][ni][half * 2 + 1];
                    dst32[gtc >> 1] = (f2key(d0) >> 16) | ((f2key(d1) >> 16) << 16);
                }
            }
        }
}

// ---------------- selection (unchanged, proven) ----------------
__global__ __launch_bounds__(512)
void select_kernel(const float* __restrict__ Q, const float* __restrict__ Tg) {
    extern __shared__ __align__(16) unsigned int sm[];
    unsigned int* hist = sm;
    unsigned long long* buf = (unsigned long long*)sm;
    unsigned int* cand = (unsigned int*)(buf + CAP);
    __shared__ float qrow_s[128];
    __shared__ unsigned int scanbuf[512];
    __shared__ unsigned int s_kth, s_cnt;
    __shared__ float sred[256];
    __shared__ float s_dmin, s_qnorm;

    int q = blockIdx.x;
    int tid = threadIdx.x;
    const uint4* row = (const uint4*)(g_key16 + (size_t)q * M);

    if (tid < 32)
        *(float4*)&qrow_s[tid * 4] = *(const float4*)&Q[(size_t)q * D + tid * 4];
    for (int i = tid; i < 32768; i += 512) hist[i] = 0u;
    __syncthreads();

    if (tid == 0) {
        float acc = 0.f;
#pragma unroll
        for (int k = 0; k < 32; k++) {
            float4 v = *(const float4*)&qrow_s[k * 4];
            acc += v.x * v.x + v.y * v.y + v.z * v.z + v.w * v.w;
        }
        s_qnorm = acc;
    }

    for (int j = tid; j < 12500; j += 512) {
        uint4 w = row[j];
        unsigned int us[4] = {w.x, w.y, w.z, w.w};
#pragma unroll
        for (int uu = 0; uu < 4; uu++) {
            unsigned int a = us[uu] & 0xFFFFu, b = us[uu] >> 16;
            atomicAdd(&hist[a >> 1], 1u << ((a & 1u) * 16));
            atomicAdd(&hist[b >> 1], 1u << ((b & 1u) * 16));
        }
    }
    __syncthreads();

    unsigned int ssum = 0u;
    for (int w = 0; w < 64; w++) {
        unsigned int v = hist[tid * 64 + w];
        ssum += (v & 0xffffu) + (v >> 16);
    }
    scanbuf[tid] = ssum;
    __syncthreads();
    for (int off = 1; off < 512; off <<= 1) {
        unsigned int a = scanbuf[tid];
        unsigned int b = (tid >= off) ? scanbuf[tid - off] : 0u;
        __syncthreads();
        scanbuf[tid] = a + b;
        __syncthreads();
    }
    unsigned int excl = (tid == 0) ? 0u : scanbuf[tid - 1];
    unsigned int incl = scanbuf[tid];
    if (excl < KNN && KNN <= (int)incl) {
        unsigned int c = excl;
        for (int w = 0; w < 64; w++) {
            unsigned int v = hist[tid * 64 + w];
            unsigned int lo = v & 0xffffu;
            if (KNN <= (int)(c + lo)) { s_kth = (unsigned int)(tid * 128 + 2 * w); break; }
            c += lo;
            unsigned int hi = v >> 16;
            if (KNN <= (int)(c + hi)) { s_kth = (unsigned int)(tid * 128 + 2 * w + 1); break; }
            c += hi;
        }
    }
    __syncthreads();
    unsigned int kth = s_kth;
    float Tedge = key2f((kth << 16) | 0xFFFFu);
    float qn = s_qnorm;
    __syncthreads();

    int n = 0;
    for (int att = 0; att < 2; att++) {
        if (tid == 0) s_cnt = 0u;
        __syncthreads();
        unsigned int th = f2key(Tedge + ((att == 0) ? 4.0f : 0.5f)) >> 16;
        for (int j = tid; j < 12500; j += 512) {
            uint4 w = row[j];
            unsigned int us[4] = {w.x, w.y, w.z, w.w};
#pragma unroll
            for (int uu = 0; uu < 4; uu++) {
                unsigned int a = us[uu] & 0xFFFFu, b = us[uu] >> 16;
                if (a <= th) {
                    unsigned int pos = atomicAdd(&s_cnt, 1u);
                    if (pos < CAP) cand[pos] = (unsigned int)(j * 8 + uu * 2);
                }
                if (b <= th) {
                    unsigned int pos = atomicAdd(&s_cnt, 1u);
                    if (pos < CAP) cand[pos] = (unsigned int)(j * 8 + uu * 2 + 1);
                }
            }
        }
        __syncthreads();
        n = (int)s_cnt;
        if (n <= CAP) break;
        __syncthreads();
    }
    if (n > CAP) n = CAP;

    for (int cc = tid; cc < n; cc += 512) {
        int j = (int)cand[cc];
        const float* trow = Tg + (size_t)j * D;
        float a0 = 0.f, a1 = 0.f, a2 = 0.f, a3 = 0.f;
#pragma unroll
        for (int k4 = 0; k4 < 32; k4++) {
            float4 tv = *(const float4*)&trow[k4 * 4];
            float4 qv = *(const float4*)&qrow_s[k4 * 4];
            a0 = fmaf(qv.x, tv.x, a0);
            a1 = fmaf(qv.y, tv.y, a1);
            a2 = fmaf(qv.z, tv.z, a2);
            a3 = fmaf(qv.w, tv.w, a3);
        }
        float d = qn + g_tn[j] - 2.f * ((a0 + a1) + (a2 + a3));
        buf[cc] = ((unsigned long long)f2key(d) << 32) | (unsigned int)j;
    }
    __syncthreads();

    int size = 128;
    while (size < n) size <<= 1;
    for (int i = tid; i < size; i += 512)
        if (i >= n) buf[i] = 0xFFFFFFFFFFFFFFFFull;
    __syncthreads();
    for (int k2 = 2; k2 <= size; k2 <<= 1) {
        for (int j2 = k2 >> 1; j2 > 0; j2 >>= 1) {
            for (int i = tid; i < size; i += 512) {
                int l = i ^ j2;
                if (l > i) {
                    unsigned long long a = buf[i], b = buf[l];
                    bool up = ((i & k2) == 0);
                    if ((a > b) == up) { buf[i] = b; buf[l] = a; }
                }
            }
            __syncthreads();
        }
    }

    if (tid == 0) s_dmin = key2f((unsigned int)(buf[0] >> 32));
    __syncthreads();
    float dmin = s_dmin;
    float myex = 0.f; int myidx = 0;
    if (tid < KNN) {
        unsigned long long e = buf[tid];
        myidx = (int)(unsigned int)(e & 0xffffffffull);
        float d = key2f((unsigned int)(e >> 32));
        myex = expf(dmin - d);
    }
    if (tid < 256) sred[tid] = (tid < KNN) ? myex : 0.f;
    __syncthreads();
    for (int off = 128; off > 0; off >>= 1) {
        if (tid < off) sred[tid] += sred[tid + off];
        __syncthreads();
    }
    float ssum2 = sred[0];
    if (tid < KNN) {
        g_emit[q * KNN + tid] = myex / ssum2;
        g_idx[q * KNN + tid] = myidx;
    }
}

// ---------------- fused trans + viterbi: blocks 0-3 viterbi, 4-255 trans slabs ----------------
__global__ __launch_bounds__(512, 2)
void tv_fused_kernel(const float* __restrict__ Tg, float* __restrict__ out) {
    extern __shared__ __align__(16) float dynf[];   // 103200 B
    int tid = threadIdx.x;

    if (blockIdx.x >= 4) {
        // ================= trans role (verbatim trans_kernel body) =================
        float* sA = dynf;
        float* sB = dynf + D * KNN;
        float* an = dynf + 2 * D * KNN;
        float* bn = an + KNN;
        __shared__ int idxA[KNN], idxB[KNN];
        int bt = blockIdx.x - 4;
        int b = bt / (TT - 1), tl = bt % (TT - 1);
        int qA = b * TT + tl, qB = qA + 1;
        if (tid < KNN) idxA[tid] = g_idx[qA * KNN + tid];
        else if (tid < 2 * KNN) idxB[tid - KNN] = g_idx[qB * KNN + (tid - KNN)];
        __syncthreads();
        for (int n = tid; n < KNN * D; n += blockDim.x) {
            int i = n / D, k = n % D;
            sA[k * KNN + i] = Tg[(size_t)idxA[i] * D + k];
            sB[k * KNN + i] = Tg[(size_t)idxB[i] * D + k];
        }
        __syncthreads();
        for (int i = tid; i < 2 * KNN; i += blockDim.x) {
            int ii = (i < KNN) ? i : (i - KNN);
            const float* sp = (i < KNN) ? sA : sB;
            float acc = 0.f;
            for (int k = 0; k < D; k++) { float x = sp[k * KNN + ii]; acc += x * x; }
            if (i < KNN) an[ii] = acc; else bn[ii] = acc;
        }
        __syncthreads();
        float* trow = g_trans + (size_t)bt * KNN * KNN;
        for (int t4 = tid; t4 < 625; t4 += blockDim.x) {
            int i0 = (t4 / 25) * 4, j0 = (t4 % 25) * 4;
            float acc[4][4] = {};
            for (int k = 0; k < D; k++) {
                float4 a  = *(const float4*)&sA[k * KNN + i0];
                float4 b4 = *(const float4*)&sB[k * KNN + j0];
                acc[0][0] += a.x * b4.x; acc[0][1] += a.x * b4.y; acc[0][2] += a.x * b4.z; acc[0][3] += a.x * b4.w;
                acc[1][0] += a.y * b4.x; acc[1][1] += a.y * b4.y; acc[1][2] += a.y * b4.z; acc[1][3] += a.y * b4.w;
                acc[2][0] += a.z * b4.x; acc[2][1] += a.z * b4.y; acc[2][2] += a.z * b4.z; acc[2][3] += a.z * b4.w;
                acc[3][0] += a.w * b4.x; acc[3][1] += a.w * b4.y; acc[3][2] += a.w * b4.z; acc[3][3] += a.w * b4.w;
            }
#pragma unroll
            for (int ii = 0; ii < 4; ii++)
#pragma unroll
                for (int jj = 0; jj < 4; jj++) {
                    int i = i0 + ii, j = j0 + jj;
                    float dd = an[i] + bn[j] - 2.f * acc[ii][jj];
                    trow[i * KNN + j] = expf(-dd);
                }
        }
        // publish slab
        __syncthreads();
        __threadfence();
        if (tid == 0) *(volatile int*)&g_flag[bt] = 1;
        return;
    }

    // ================= viterbi role (R12 measured-best body + flag waits) =================
    float* trbuf0 = dynf;
    float* trbuf1 = dynf + KNN * KNN;
    int b = blockIdx.x;
    int j = tid & 127, s = tid >> 7;
    int lane = tid & 31;
    __shared__ float v[128];
    __shared__ float part[4][128];
    __shared__ unsigned char parti[4][128];
    __shared__ float wmax[4];
    __shared__ unsigned char bp[TT - 1][KNN];
    __shared__ int path[TT];
    int i0 = s * 25;
    if (s == 0) v[j] = (j < KNN) ? g_emit[(b * TT) * KNN + j] : 0.f;

    uint4 pf4[5];

#define WAIT_SLAB(tt)                                                                  \
    if ((tt) < TT) {                                                                   \
        volatile int* f_ = &g_flag[b * (TT - 1) + (tt) - 1];                           \
        while (*f_ == 0) {}                                                            \
        __threadfence();                                                               \
    }

#define LDG_SLAB(tt)                                                                   \
    if ((tt) < TT) {                                                                   \
        const uint4* sp_ = (const uint4*)(g_trans                                      \
            + (size_t)(b * (TT - 1) + (tt) - 1) * (KNN * KNN));                        \
        _Pragma("unroll")                                                              \
        for (int r_ = 0; r_ < 5; r_++) {                                               \
            int li_ = r_ * 512 + tid;                                                  \
            if (li_ < 2500) pf4[r_] = __ldg(&sp_[li_]);                                \
        }                                                                              \
    }

#define STS_SLAB(tt)                                                                   \
    if ((tt) < TT) {                                                                   \
        uint4* dp_ = (uint4*)(((tt) & 1) ? trbuf1 : trbuf0);                           \
        _Pragma("unroll")                                                              \
        for (int r_ = 0; r_ < 5; r_++) {                                               \
            int li_ = r_ * 512 + tid;                                                  \
            if (li_ < 2500) dp_[li_] = pf4[r_];                                        \
        }                                                                              \
    }

    WAIT_SLAB(1);
    LDG_SLAB(1);
    STS_SLAB(1);
    WAIT_SLAB(2);
    LDG_SLAB(2);
    __syncthreads();

    for (int t = 1; t < TT; t++) {
        STS_SLAB(t + 1);
        WAIT_SLAB(t + 2);
        LDG_SLAB(t + 2);
        float em = (s == 0 && j < KNN) ? __ldg(&g_emit[(b * TT + t) * KNN + j]) : 0.f;

        const float* trc = ((t & 1) ? trbuf1 : trbuf0) + j + i0 * KNN;
        float best = -1.f; int back = 0;
        if (j < KNN) {
#pragma unroll
            for (int ii = 0; ii < 25; ii++) {
                float x = v[i0 + ii] * trc[ii * KNN];
                if (x > best) { best = x; back = i0 + ii; }
            }
        }
        part[s][j] = best; parti[s][j] = (unsigned char)back;
        __syncthreads();
        float vn = 0.f;
        if (s == 0) {
            float bb = part[0][j]; int bk = parti[0][j];
#pragma unroll
            for (int ss = 1; ss < 4; ss++)
                if (part[ss][j] > bb) { bb = part[ss][j]; bk = parti[ss][j]; }
            if (j < KNN) bp[t - 1][j] = (unsigned char)bk;
            vn = (j < KNN) ? bb * em : 0.f;
            float w = vn;
#pragma unroll
            for (int off = 16; off > 0; off >>= 1)
                w = fmaxf(w, __shfl_xor_sync(0xFFFFFFFFu, w, off));
            if (lane == 0) wmax[(j >> 5)] = w;
        }
        __syncthreads();
        float m = fmaxf(fmaxf(fmaxf(wmax[0], wmax[1]), fmaxf(wmax[2], wmax[3])), 1e-30f);
        if (s == 0) v[j] = vn / m;
        __syncthreads();
    }
#undef WAIT_SLAB
#undef LDG_SLAB
#undef STS_SLAB

    if (tid == 0) {
        float bv = v[0]; int last = 0;
        for (int jj = 1; jj < KNN; jj++) if (v[jj] > bv) { bv = v[jj]; last = jj; }
        path[TT - 1] = last;
        int idx = last;
        for (int t = TT - 2; t >= 0; t--) { idx = bp[t][idx]; path[t] = idx; }
    }
    __syncthreads();
    for (int n = tid; n < TT * D; n += 512) {
        int t = n / D, d2 = n % D;
        int row = g_idx[(b * TT + t) * KNN + path[t]];
        out[(size_t)(b * TT + t) * D + d2] = Tg[(size_t)row * D + d2];
    }
}

// ---------------- launch ----------------
extern "C" void kernel_launch(void* const* d_in, const int* in_sizes, int n_in,
                              void* d_out, int out_size) {
    (void)in_sizes; (void)n_in; (void)out_size;
    const float* Q  = (const float*)d_in[0];
    const float* Tg = (const float*)d_in[1];
    float* out = (float*)d_out;

    const int dist_smem = 2 * 128 * TSTR * 2;                             // 69632 B
    const int sel_smem  = 131072;
    const int tv_smem   = (2 * D * KNN + 2 * KNN) * (int)sizeof(float);   // 103200 B
    cudaFuncSetAttribute(dist_bf16_kernel, cudaFuncAttributeMaxDynamicSharedMemorySize, dist_smem);
    cudaFuncSetAttribute(select_kernel, cudaFuncAttributeMaxDynamicSharedMemorySize, sel_smem);
    cudaFuncSetAttribute(tv_fused_kernel, cudaFuncAttributeMaxDynamicSharedMemorySize, tv_smem);

    dist_bf16_kernel<<<dim3((M + 127) / 128, NQ / 128), 256, dist_smem>>>(Q, Tg);  // 0
    select_kernel<<<NQ, 512, sel_smem>>>(Q, Tg);                                   // 1
    reset_kernel<<<1, 256>>>();                                                    // 2
    tv_fused_kernel<<<4 + NTRANS, 512, tv_smem>>>(Tg, out);                        // 3 (profiled)
}

// round 17
// speedup vs baseline: 1.1391x; 1.1391x over previous
#include <cuda_runtime.h>
#include <cuda_bf16.h>
#include <cstdint>

#define M    100000
#define NQ   256
#define D    128
#define KNN  100
#define BB   4
#define TT   64
#define CAP  4096
#define TSTR 136          // smem tile stride in bf16 elems

// ---------------- device scratch ----------------
static __device__ float          g_tn[M];
static __device__ unsigned short g_key16[(size_t)NQ * M];  // 51.2 MB truncated keys
static __device__ int            g_idx[NQ * KNN];
static __device__ float          g_emit[NQ * KNN];
static __device__ float          g_trans[(size_t)BB * (TT - 1) * KNN * KNN];

__device__ __forceinline__ unsigned int f2key(float f) {
    unsigned int u = __float_as_uint(f);
    return (u & 0x80000000u) ? ~u : (u | 0x80000000u);
}
__device__ __forceinline__ float key2f(unsigned int k) {
    unsigned int u = (k & 0x80000000u) ? (k & 0x7fffffffu) : ~k;
    return __uint_as_float(u);
}

__device__ __forceinline__ void mma_bf16(float* d, const unsigned* a, const unsigned* b) {
    asm volatile(
        "mma.sync.aligned.m16n8k16.row.col.f32.bf16.bf16.f32 "
        "{%0,%1,%2,%3}, {%4,%5,%6,%7}, {%8,%9}, {%0,%1,%2,%3};"
        : "+f"(d[0]), "+f"(d[1]), "+f"(d[2]), "+f"(d[3])
        : "r"(a[0]), "r"(a[1]), "r"(a[2]), "r"(a[3]), "r"(b[0]), "r"(b[1]));
}

// ---------------- fused dist: fp32 load + bf16 convert + norms + mma -> u16 keys ----------------
// ONE change vs R12: min-blocks 3 to lift occupancy (regs 92 -> <=85)
__global__ __launch_bounds__(256, 3)
void dist_bf16_kernel(const float* __restrict__ Q, const float* __restrict__ Tg) {
    extern __shared__ __align__(16) char dyn[];
    __nv_bfloat16* Qs = (__nv_bfloat16*)dyn;               // [128][TSTR]
    __nv_bfloat16* Ts = Qs + 128 * TSTR;
    __shared__ float s_qn[128], s_tn[128];
    int tid = threadIdx.x;
    int lane = tid & 31;
    int q0 = blockIdx.y * 128, t0 = blockIdx.x * 128;

    for (int it = 0; it < 16; it++) {
        int r = it * 8 + (tid >> 5);
        int c4 = lane * 4;
        float4 v = *(const float4*)&Q[(size_t)(q0 + r) * D + c4];
        float pn = v.x * v.x + v.y * v.y + v.z * v.z + v.w * v.w;
        __nv_bfloat162 p0 = __floats2bfloat162_rn(v.x, v.y);
        __nv_bfloat162 p1 = __floats2bfloat162_rn(v.z, v.w);
        *(uint2*)&Qs[r * TSTR + c4] = make_uint2(*(unsigned*)&p0, *(unsigned*)&p1);
#pragma unroll
        for (int off = 16; off > 0; off >>= 1) pn += __shfl_xor_sync(0xFFFFFFFFu, pn, off);
        if (lane == 0) s_qn[r] = pn;
        float4 tv = make_float4(0.f, 0.f, 0.f, 0.f);
        if (t0 + r < M) tv = *(const float4*)&Tg[(size_t)(t0 + r) * D + c4];
        float tn = tv.x * tv.x + tv.y * tv.y + tv.z * tv.z + tv.w * tv.w;
        __nv_bfloat162 t0b = __floats2bfloat162_rn(tv.x, tv.y);
        __nv_bfloat162 t1b = __floats2bfloat162_rn(tv.z, tv.w);
        *(uint2*)&Ts[r * TSTR + c4] = make_uint2(*(unsigned*)&t0b, *(unsigned*)&t1b);
#pragma unroll
        for (int off = 16; off > 0; off >>= 1) tn += __shfl_xor_sync(0xFFFFFFFFu, tn, off);
        if (lane == 0) s_tn[r] = tn;
    }

    if (blockIdx.y == 0 && tid < 128 && t0 + tid < M) {
        const float4* p = (const float4*)(Tg + (size_t)(t0 + tid) * D);
        float acc = 0.f;
#pragma unroll
        for (int k = 0; k < 32; k++) {
            float4 v = p[k];
            acc += v.x * v.x + v.y * v.y + v.z * v.z + v.w * v.w;
        }
        g_tn[t0 + tid] = acc;
    }
    __syncthreads();

    int wid = tid >> 5;
    int g = lane >> 2, t = lane & 3;
    int m0 = (wid >> 1) * 32, n0 = (wid & 1) * 64;

    float acc[2][8][4];
#pragma unroll
    for (int mi = 0; mi < 2; mi++)
#pragma unroll
        for (int ni = 0; ni < 8; ni++)
#pragma unroll
            for (int r = 0; r < 4; r++) acc[mi][ni][r] = 0.f;

#pragma unroll
    for (int ks = 0; ks < 8; ks++) {
        int k0 = ks * 16;
        unsigned a[2][4], b[8][2];
#pragma unroll
        for (int mi = 0; mi < 2; mi++) {
            const __nv_bfloat16* base = &Qs[(m0 + mi * 16 + g) * TSTR + k0 + 2 * t];
            a[mi][0] = *(const unsigned*)(base);
            a[mi][1] = *(const unsigned*)(base + 8 * TSTR);
            a[mi][2] = *(const unsigned*)(base + 8);
            a[mi][3] = *(const unsigned*)(base + 8 * TSTR + 8);
        }
#pragma unroll
        for (int ni = 0; ni < 8; ni++) {
            const __nv_bfloat16* base = &Ts[(n0 + ni * 8 + g) * TSTR + k0 + 2 * t];
            b[ni][0] = *(const unsigned*)(base);
            b[ni][1] = *(const unsigned*)(base + 8);
        }
#pragma unroll
        for (int mi = 0; mi < 2; mi++)
#pragma unroll
            for (int ni = 0; ni < 8; ni++)
                mma_bf16(acc[mi][ni], a[mi], b[ni]);
    }

#pragma unroll
    for (int mi = 0; mi < 2; mi++)
#pragma unroll
        for (int half = 0; half < 2; half++) {
            int qr = m0 + mi * 16 + g + half * 8;
            float qn = s_qn[qr];
            unsigned int* dst32 = (unsigned int*)(g_key16 + (size_t)(q0 + qr) * M);
#pragma unroll
            for (int ni = 0; ni < 8; ni++) {
                int tc = n0 + ni * 8 + 2 * t;
                int gtc = t0 + tc;
                if (gtc + 1 < M) {
                    float d0 = qn + s_tn[tc]     - 2.f * acc[mi][ni][half * 2 + 0];
                    float d1 = qn + s_tn[tc + 1] - 2.f * acc[mi][ni][half * 2 + 1];
                    dst32[gtc >> 1] = (f2key(d0) >> 16) | ((f2key(d1) >> 16) << 16);
                }
            }
        }
}

// ---------------- selection (unchanged, proven) ----------------
__global__ __launch_bounds__(512)
void select_kernel(const float* __restrict__ Q, const float* __restrict__ Tg) {
    extern __shared__ __align__(16) unsigned int sm[];
    unsigned int* hist = sm;
    unsigned long long* buf = (unsigned long long*)sm;
    unsigned int* cand = (unsigned int*)(buf + CAP);
    __shared__ float qrow_s[128];
    __shared__ unsigned int scanbuf[512];
    __shared__ unsigned int s_kth, s_cnt;
    __shared__ float sred[256];
    __shared__ float s_dmin, s_qnorm;

    int q = blockIdx.x;
    int tid = threadIdx.x;
    const uint4* row = (const uint4*)(g_key16 + (size_t)q * M);

    if (tid < 32)
        *(float4*)&qrow_s[tid * 4] = *(const float4*)&Q[(size_t)q * D + tid * 4];
    for (int i = tid; i < 32768; i += 512) hist[i] = 0u;
    __syncthreads();

    if (tid == 0) {
        float acc = 0.f;
#pragma unroll
        for (int k = 0; k < 32; k++) {
            float4 v = *(const float4*)&qrow_s[k * 4];
            acc += v.x * v.x + v.y * v.y + v.z * v.z + v.w * v.w;
        }
        s_qnorm = acc;
    }

    for (int j = tid; j < 12500; j += 512) {
        uint4 w = row[j];
        unsigned int us[4] = {w.x, w.y, w.z, w.w};
#pragma unroll
        for (int uu = 0; uu < 4; uu++) {
            unsigned int a = us[uu] & 0xFFFFu, b = us[uu] >> 16;
            atomicAdd(&hist[a >> 1], 1u << ((a & 1u) * 16));
            atomicAdd(&hist[b >> 1], 1u << ((b & 1u) * 16));
        }
    }
    __syncthreads();

    unsigned int ssum = 0u;
    for (int w = 0; w < 64; w++) {
        unsigned int v = hist[tid * 64 + w];
        ssum += (v & 0xffffu) + (v >> 16);
    }
    scanbuf[tid] = ssum;
    __syncthreads();
    for (int off = 1; off < 512; off <<= 1) {
        unsigned int a = scanbuf[tid];
        unsigned int b = (tid >= off) ? scanbuf[tid - off] : 0u;
        __syncthreads();
        scanbuf[tid] = a + b;
        __syncthreads();
    }
    unsigned int excl = (tid == 0) ? 0u : scanbuf[tid - 1];
    unsigned int incl = scanbuf[tid];
    if (excl < KNN && KNN <= (int)incl) {
        unsigned int c = excl;
        for (int w = 0; w < 64; w++) {
            unsigned int v = hist[tid * 64 + w];
            unsigned int lo = v & 0xffffu;
            if (KNN <= (int)(c + lo)) { s_kth = (unsigned int)(tid * 128 + 2 * w); break; }
            c += lo;
            unsigned int hi = v >> 16;
            if (KNN <= (int)(c + hi)) { s_kth = (unsigned int)(tid * 128 + 2 * w + 1); break; }
            c += hi;
        }
    }
    __syncthreads();
    unsigned int kth = s_kth;
    float Tedge = key2f((kth << 16) | 0xFFFFu);
    float qn = s_qnorm;
    __syncthreads();

    int n = 0;
    for (int att = 0; att < 2; att++) {
        if (tid == 0) s_cnt = 0u;
        __syncthreads();
        unsigned int th = f2key(Tedge + ((att == 0) ? 4.0f : 0.5f)) >> 16;
        for (int j = tid; j < 12500; j += 512) {
            uint4 w = row[j];
            unsigned int us[4] = {w.x, w.y, w.z, w.w};
#pragma unroll
            for (int uu = 0; uu < 4; uu++) {
                unsigned int a = us[uu] & 0xFFFFu, b = us[uu] >> 16;
                if (a <= th) {
                    unsigned int pos = atomicAdd(&s_cnt, 1u);
                    if (pos < CAP) cand[pos] = (unsigned int)(j * 8 + uu * 2);
                }
                if (b <= th) {
                    unsigned int pos = atomicAdd(&s_cnt, 1u);
                    if (pos < CAP) cand[pos] = (unsigned int)(j * 8 + uu * 2 + 1);
                }
            }
        }
        __syncthreads();
        n = (int)s_cnt;
        if (n <= CAP) break;
        __syncthreads();
    }
    if (n > CAP) n = CAP;

    for (int cc = tid; cc < n; cc += 512) {
        int j = (int)cand[cc];
        const float* trow = Tg + (size_t)j * D;
        float a0 = 0.f, a1 = 0.f, a2 = 0.f, a3 = 0.f;
#pragma unroll
        for (int k4 = 0; k4 < 32; k4++) {
            float4 tv = *(const float4*)&trow[k4 * 4];
            float4 qv = *(const float4*)&qrow_s[k4 * 4];
            a0 = fmaf(qv.x, tv.x, a0);
            a1 = fmaf(qv.y, tv.y, a1);
            a2 = fmaf(qv.z, tv.z, a2);
            a3 = fmaf(qv.w, tv.w, a3);
        }
        float d = qn + g_tn[j] - 2.f * ((a0 + a1) + (a2 + a3));
        buf[cc] = ((unsigned long long)f2key(d) << 32) | (unsigned int)j;
    }
    __syncthreads();

    int size = 128;
    while (size < n) size <<= 1;
    for (int i = tid; i < size; i += 512)
        if (i >= n) buf[i] = 0xFFFFFFFFFFFFFFFFull;
    __syncthreads();
    for (int k2 = 2; k2 <= size; k2 <<= 1) {
        for (int j2 = k2 >> 1; j2 > 0; j2 >>= 1) {
            for (int i = tid; i < size; i += 512) {
                int l = i ^ j2;
                if (l > i) {
                    unsigned long long a = buf[i], b = buf[l];
                    bool up = ((i & k2) == 0);
                    if ((a > b) == up) { buf[i] = b; buf[l] = a; }
                }
            }
            __syncthreads();
        }
    }

    if (tid == 0) s_dmin = key2f((unsigned int)(buf[0] >> 32));
    __syncthreads();
    float dmin = s_dmin;
    float myex = 0.f; int myidx = 0;
    if (tid < KNN) {
        unsigned long long e = buf[tid];
        myidx = (int)(unsigned int)(e & 0xffffffffull);
        float d = key2f((unsigned int)(e >> 32));
        myex = expf(dmin - d);
    }
    if (tid < 256) sred[tid] = (tid < KNN) ? myex : 0.f;
    __syncthreads();
    for (int off = 128; off > 0; off >>= 1) {
        if (tid < off) sred[tid] += sred[tid + off];
        __syncthreads();
    }
    float ssum2 = sred[0];
    if (tid < KNN) {
        g_emit[q * KNN + tid] = myex / ssum2;
        g_idx[q * KNN + tid] = myidx;
    }
}

// ---------------- transitions (unchanged, proven 47us) ----------------
__global__ void trans_kernel(const float* __restrict__ Tg) {
    extern __shared__ __align__(16) float s[];
    float* sA = s;
    float* sB = s + D * KNN;
    float* an = s + 2 * D * KNN;
    float* bn = an + KNN;
    __shared__ int idxA[KNN], idxB[KNN];
    int bt = blockIdx.x;
    int b = bt / (TT - 1), tl = bt % (TT - 1);
    int qA = b * TT + tl, qB = qA + 1;
    int tid = threadIdx.x;
    if (tid < KNN) idxA[tid] = g_idx[qA * KNN + tid];
    else if (tid < 2 * KNN) idxB[tid - KNN] = g_idx[qB * KNN + (tid - KNN)];
    __syncthreads();
    for (int n = tid; n < KNN * D; n += blockDim.x) {
        int i = n / D, k = n % D;
        sA[k * KNN + i] = Tg[(size_t)idxA[i] * D + k];
        sB[k * KNN + i] = Tg[(size_t)idxB[i] * D + k];
    }
    __syncthreads();
    for (int i = tid; i < 2 * KNN; i += blockDim.x) {
        int ii = (i < KNN) ? i : (i - KNN);
        const float* sp = (i < KNN) ? sA : sB;
        float acc = 0.f;
        for (int k = 0; k < D; k++) { float x = sp[k * KNN + ii]; acc += x * x; }
        if (i < KNN) an[ii] = acc; else bn[ii] = acc;
    }
    __syncthreads();
    float* trow = g_trans + (size_t)bt * KNN * KNN;
    for (int t4 = tid; t4 < 625; t4 += blockDim.x) {
        int i0 = (t4 / 25) * 4, j0 = (t4 % 25) * 4;
        float acc[4][4] = {};
        for (int k = 0; k < D; k++) {
            float4 a  = *(const float4*)&sA[k * KNN + i0];
            float4 b4 = *(const float4*)&sB[k * KNN + j0];
            acc[0][0] += a.x * b4.x; acc[0][1] += a.x * b4.y; acc[0][2] += a.x * b4.z; acc[0][3] += a.x * b4.w;
            acc[1][0] += a.y * b4.x; acc[1][1] += a.y * b4.y; acc[1][2] += a.y * b4.z; acc[1][3] += a.y * b4.w;
            acc[2][0] += a.z * b4.x; acc[2][1] += a.z * b4.y; acc[2][2] += a.z * b4.z; acc[2][3] += a.z * b4.w;
            acc[3][0] += a.w * b4.x; acc[3][1] += a.w * b4.y; acc[3][2] += a.w * b4.z; acc[3][3] += a.w * b4.w;
        }
#pragma unroll
        for (int ii = 0; ii < 4; ii++)
#pragma unroll
            for (int jj = 0; jj < 4; jj++) {
                int i = i0 + ii, j = j0 + jj;
                float dd = an[i] + bn[j] - 2.f * acc[ii][jj];
                trow[i * KNN + j] = expf(-dd);
            }
    }
}

// ---------------- viterbi: R12 measured-best (104.8us), verbatim ----------------
__global__ __launch_bounds__(512)
void viterbi_kernel(const float* __restrict__ Tg, float* __restrict__ out) {
    extern __shared__ __align__(16) float trdyn[];   // 2 x 10000 floats
    float* trbuf0 = trdyn;
    float* trbuf1 = trdyn + KNN * KNN;
    int b = blockIdx.x;
    int tid = threadIdx.x;
    int j = tid & 127, s = tid >> 7;
    int lane = tid & 31;
    __shared__ float v[128];
    __shared__ float part[4][128];
    __shared__ unsigned char parti[4][128];
    __shared__ float wmax[4];
    __shared__ unsigned char bp[TT - 1][KNN];
    __shared__ int path[TT];
    int i0 = s * 25;
    if (s == 0) v[j] = (j < KNN) ? g_emit[(b * TT) * KNN + j] : 0.f;

    uint4 pf4[5];

#define LDG_SLAB(tt)                                                                   \
    if ((tt) < TT) {                                                                   \
        const uint4* sp_ = (const uint4*)(g_trans                                      \
            + (size_t)(b * (TT - 1) + (tt) - 1) * (KNN * KNN));                        \
        _Pragma("unroll")                                                              \
        for (int r_ = 0; r_ < 5; r_++) {                                               \
            int li_ = r_ * 512 + tid;                                                  \
            if (li_ < 2500) pf4[r_] = __ldg(&sp_[li_]);                                \
        }                                                                              \
    }

#define STS_SLAB(tt)                                                                   \
    if ((tt) < TT) {                                                                   \
        uint4* dp_ = (uint4*)(((tt) & 1) ? trbuf1 : trbuf0);                           \
        _Pragma("unroll")                                                              \
        for (int r_ = 0; r_ < 5; r_++) {                                               \
            int li_ = r_ * 512 + tid;                                                  \
            if (li_ < 2500) dp_[li_] = pf4[r_];                                        \
        }                                                                              \
    }

    LDG_SLAB(1);
    STS_SLAB(1);
    LDG_SLAB(2);
    __syncthreads();

    for (int t = 1; t < TT; t++) {
        STS_SLAB(t + 1);
        LDG_SLAB(t + 2);
        float em = (s == 0 && j < KNN) ? __ldg(&g_emit[(b * TT + t) * KNN + j]) : 0.f;

        const float* trc = ((t & 1) ? trbuf1 : trbuf0) + j + i0 * KNN;
        float best = -1.f; int back = 0;
        if (j < KNN) {
#pragma unroll
            for (int ii = 0; ii < 25; ii++) {
                float x = v[i0 + ii] * trc[ii * KNN];
                if (x > best) { best = x; back = i0 + ii; }
            }
        }
        part[s][j] = best; parti[s][j] = (unsigned char)back;
        __syncthreads();
        float vn = 0.f;
        if (s == 0) {
            float bb = part[0][j]; int bk = parti[0][j];
#pragma unroll
            for (int ss = 1; ss < 4; ss++)
                if (part[ss][j] > bb) { bb = part[ss][j]; bk = parti[ss][j]; }
            if (j < KNN) bp[t - 1][j] = (unsigned char)bk;
            vn = (j < KNN) ? bb * em : 0.f;
            float w = vn;
#pragma unroll
            for (int off = 16; off > 0; off >>= 1)
                w = fmaxf(w, __shfl_xor_sync(0xFFFFFFFFu, w, off));
            if (lane == 0) wmax[(j >> 5)] = w;
        }
        __syncthreads();
        float m = fmaxf(fmaxf(fmaxf(wmax[0], wmax[1]), fmaxf(wmax[2], wmax[3])), 1e-30f);
        if (s == 0) v[j] = vn / m;
        __syncthreads();
    }
#undef LDG_SLAB
#undef STS_SLAB

    if (tid == 0) {
        float bv = v[0]; int last = 0;
        for (int jj = 1; jj < KNN; jj++) if (v[jj] > bv) { bv = v[jj]; last = jj; }
        path[TT - 1] = last;
        int idx = last;
        for (int t = TT - 2; t >= 0; t--) { idx = bp[t][idx]; path[t] = idx; }
    }
    __syncthreads();
    for (int n = tid; n < TT * D; n += 512) {
        int t = n / D, d2 = n % D;
        int row = g_idx[(b * TT + t) * KNN + path[t]];
        out[(size_t)(b * TT + t) * D + d2] = Tg[(size_t)row * D + d2];
    }
}

// ---------------- launch ----------------
extern "C" void kernel_launch(void* const* d_in, const int* in_sizes, int n_in,
                              void* d_out, int out_size) {
    (void)in_sizes; (void)n_in; (void)out_size;
    const float* Q  = (const float*)d_in[0];
    const float* Tg = (const float*)d_in[1];
    float* out = (float*)d_out;

    const int trans_smem = (2 * D * KNN + 2 * KNN) * (int)sizeof(float);   // 103200 B
    const int dist_smem  = 2 * 128 * TSTR * 2;                             // 69632 B
    const int sel_smem   = 131072;
    const int vit_smem   = 2 * KNN * KNN * (int)sizeof(float);             // 80000 B
    cudaFuncSetAttribute(trans_kernel, cudaFuncAttributeMaxDynamicSharedMemorySize, trans_smem);
    cudaFuncSetAttribute(dist_bf16_kernel, cudaFuncAttributeMaxDynamicSharedMemorySize, dist_smem);
    cudaFuncSetAttribute(select_kernel, cudaFuncAttributeMaxDynamicSharedMemorySize, sel_smem);
    cudaFuncSetAttribute(viterbi_kernel, cudaFuncAttributeMaxDynamicSharedMemorySize, vit_smem);

    dist_bf16_kernel<<<dim3((M + 127) / 128, NQ / 128), 256, dist_smem>>>(Q, Tg);  // 0
    select_kernel<<<NQ, 512, sel_smem>>>(Q, Tg);                                   // 1
    trans_kernel<<<BB * (TT - 1), 512, trans_smem>>>(Tg);                          // 2
    viterbi_kernel<<<BB, 512, vit_smem>>>(Tg, out);                                // 3 (profiled)
}